// round 12
// baseline (speedup 1.0000x reference)
#include <cuda_runtime.h>

// EfronLossPenalty — bucketized Efron Cox loss, times in [0, 8192).
// Only per-bucket (d, ers, rss) matter; block log-sum via falling factorial
// -> cancellation-free float Stirling difference.
//
// Accumulation (R9-proven hot loop + event count): ONE branch-free 32-bit RED
// per element:
//   bank 0 (non-events): fix16 total-risk sum
//   bank 1 (events):     (count << 24) | fix10 event-risk sum
// k_accum also computes g_nev and g_elr and zeroes out[] -> k_post needs only
// ONE global barrier (suffix-scan publish); each post block contributes its
// terms directly to out via atomicAdd. (R11: post geometry is latency-
// invariant, so the win must come from removing a barrier, not reshaping.)

#define NBINS 8192
#define NREP  16
#define BANK  (NREP * NBINS)
#define FIX_NE 65536.0f
#define FIX_EV 1024.0f
#define POST_BLOCKS 64
#define POST_THREADS 128

// Static scratch — zero at module load; every launch restores the all-zero
// invariant before exiting (graph-replay safe).
__device__ unsigned g_C[2 * BANK];
__device__ float g_chunk[POST_BLOCKS];
__device__ float g_elr;
__device__ float g_nev;
__device__ unsigned g_done1;
__device__ unsigned g_done2;

__device__ __forceinline__ float block_reduce_sum(float v) {
    __shared__ float s[32];
    int lane = threadIdx.x & 31;
    int wid  = threadIdx.x >> 5;
    #pragma unroll
    for (int o = 16; o > 0; o >>= 1) v += __shfl_down_sync(0xffffffffu, v, o);
    if (lane == 0) s[wid] = v;
    __syncthreads();
    int nw = (blockDim.x + 31) >> 5;
    v = (threadIdx.x < nw) ? s[threadIdx.x] : 0.0f;
    if (wid == 0) {
        #pragma unroll
        for (int o = 16; o > 0; o >>= 1) v += __shfl_down_sync(0xffffffffu, v, o);
    }
    __syncthreads();   // protect s[] against reuse
    return v;          // valid in thread 0
}

__device__ __forceinline__ void accum_one(int t, int e, float x, unsigned repbase,
                                          float& elr, int& ec) {
    float w = __expf(x);
    float scale = e ? FIX_EV : FIX_NE;            // FSEL
    unsigned wi = (unsigned)fmaf(w, scale, 0.5f); // one FFMA + one F2I
    unsigned val = wi + ((unsigned)e << 24);      // count tag (0 for non-events)
    unsigned idx = repbase + (unsigned)t + (unsigned)e * (unsigned)BANK;
    atomicAdd(&g_C[idx], val);                    // no return use -> REDG.32
    elr += e ? x : 0.0f;
    ec  += e;
}

__global__ void __launch_bounds__(256) k_accum(
        const int* __restrict__ times, const int* __restrict__ events,
        const float* __restrict__ lr, int n,
        float* __restrict__ out, int out_n) {
    int tid = blockIdx.x * blockDim.x + threadIdx.x;
    int stride = gridDim.x * blockDim.x;
    unsigned repbase = (((unsigned)(tid >> 5)) & (NREP - 1)) * NBINS;

    const int4*   t4 = (const int4*)times;
    const int4*   e4 = (const int4*)events;
    const float4* l4 = (const float4*)lr;
    int n4 = n >> 2;

    float elr = 0.0f;
    int ec = 0;
    int i = tid;
    // 8 elements per iteration: two int4/float4 triplets in flight (deeper MLP)
    for (; i + stride < n4; i += 2 * stride) {
        int4   ta = t4[i],          tb = t4[i + stride];
        int4   ea = e4[i],          eb = e4[i + stride];
        float4 la = l4[i],          lb = l4[i + stride];
        accum_one(ta.x, ea.x, la.x, repbase, elr, ec);
        accum_one(ta.y, ea.y, la.y, repbase, elr, ec);
        accum_one(ta.z, ea.z, la.z, repbase, elr, ec);
        accum_one(ta.w, ea.w, la.w, repbase, elr, ec);
        accum_one(tb.x, eb.x, lb.x, repbase, elr, ec);
        accum_one(tb.y, eb.y, lb.y, repbase, elr, ec);
        accum_one(tb.z, eb.z, lb.z, repbase, elr, ec);
        accum_one(tb.w, eb.w, lb.w, repbase, elr, ec);
    }
    for (; i < n4; i += stride) {
        int4   tv = t4[i];
        int4   ev = e4[i];
        float4 lv = l4[i];
        accum_one(tv.x, ev.x, lv.x, repbase, elr, ec);
        accum_one(tv.y, ev.y, lv.y, repbase, elr, ec);
        accum_one(tv.z, ev.z, lv.z, repbase, elr, ec);
        accum_one(tv.w, ev.w, lv.w, repbase, elr, ec);
    }
    int base = n4 << 2;
    int rem  = n - base;
    if (tid < rem) accum_one(times[base + tid], events[base + tid], lr[base + tid],
                             repbase, elr, ec);

    float bsum = block_reduce_sum(elr);
    if (threadIdx.x == 0 && bsum != 0.0f) atomicAdd(&g_elr, bsum);
    float csum = block_reduce_sum((float)ec);
    if (threadIdx.x == 0 && csum != 0.0f) atomicAdd(&g_nev, csum);

    // zero the output so k_post blocks can accumulate into it (poisoned 0xAA)
    if (blockIdx.x == 0) {
        for (int j = threadIdx.x; j < out_n; j += blockDim.x) out[j] = 0.0f;
    }
}

// Post-pass: replica reduce (+ re-zero), ONE cross-block suffix-scan barrier,
// per-bucket Efron terms (float Stirling), per-block atomic contribution to
// out. 64 blocks x 128 threads, one bucket per thread; all blocks resident.
__global__ void __launch_bounds__(POST_THREADS) k_post(float* __restrict__ out, int out_n) {
    int b = blockIdx.x * POST_THREADS + threadIdx.x;   // bucket 0..8191

    __shared__ float s_invnev, s_elr;
    if (threadIdx.x == 0) {
        s_invnev = 1.0f / fmaxf(g_nev, 1.0f);   // finalized by k_accum
        s_elr    = g_elr;
    }

    // --- phase 1: reduce over replicas + banks, restore zeros ---
    unsigned ne_fix = 0u;       // fix16 non-event risk
    unsigned cnt = 0u;          // event count
    unsigned ers_fix = 0u;      // fix10 event risk
    #pragma unroll
    for (int r = 0; r < NREP; r++) {
        int idx = r * NBINS + b;
        unsigned v0 = g_C[idx];          g_C[idx] = 0u;
        unsigned v1 = g_C[idx + BANK];   g_C[idx + BANK] = 0u;
        ne_fix  += v0;
        cnt     += v1 >> 24;
        ers_fix += v1 & 0x00FFFFFFu;
    }
    int   d    = (int)cnt;
    float ers  = (float)ers_fix * (1.0f / FIX_EV);
    float risk = (float)ne_fix * (1.0f / FIX_NE) + ers;

    // --- phase 2: cross-block suffix scan of risk (the one barrier) ---
    float csum = block_reduce_sum(risk);
    if (threadIdx.x == 0) {
        g_chunk[blockIdx.x] = csum;
        __threadfence();
        atomicAdd(&g_done1, 1u);
        while (*((volatile unsigned*)&g_done1) < gridDim.x) { }
    }
    __syncthreads();
    __threadfence();

    float suffix_base = 0.0f;
    for (int j = blockIdx.x + 1; j < POST_BLOCKS; j++) suffix_base += g_chunk[j];

    __shared__ float sv[POST_THREADS];
    sv[threadIdx.x] = risk;
    __syncthreads();
    for (int off = 1; off < POST_THREADS; off <<= 1) {
        float add = (threadIdx.x + off < POST_THREADS) ? sv[threadIdx.x + off] : 0.0f;
        __syncthreads();
        sv[threadIdx.x] += add;
        __syncthreads();
    }
    float rss = suffix_base + sv[threadIdx.x];   // inclusive suffix sum at bucket b

    // --- phase 3: Efron terms (all-float, cancellation-free) ---
    float term = 0.0f;
    if (d == 1) {
        term = logf(rss + 1e-12f);
    } else if (d > 1) {
        float s  = ers / (float)d;
        float x  = rss / s;
        float a  = x + 1.0f;
        float bb = x - (float)d + 1.0f;
        if (bb > 0.5f) {
            // F(z) = (z-1/2)ln z - z + 1/(12z); F(a)-F(b) without cancellation:
            float la = logf(a), lb = logf(bb);
            float L  = 0.5f * (la + lb);
            float m  = 0.5f * (a + bb);
            float dlt = log1pf((float)d / bb);
            term = (float)d * (logf(s) + L - 1.0f)
                 + (m - 0.5f) * dlt
                 + (1.0f / 12.0f) * (1.0f / a - 1.0f / bb);
        } else {   // near-clamp fallback (matches reference per-term max(.,eps))
            float sum = 0.0f;
            for (int l = 0; l < d; l++)
                sum += __logf(fmaxf(rss - (float)l * s, 1e-12f));
            term = sum;
        }
    }

    // --- phase 4: direct atomic contribution to out (no second barrier) ---
    float tsum = block_reduce_sum(term);
    if (threadIdx.x == 0) {
        float contrib = tsum * s_invnev;
        if (blockIdx.x == 0) contrib += (-s_elr) * s_invnev;
        if (contrib != 0.0f) {
            for (int j = 0; j < out_n; j++) atomicAdd(&out[j], contrib);
        }
        // reset bookkeeping: last finisher restores the all-zero invariant
        __threadfence();
        unsigned p2 = atomicAdd(&g_done2, 1u);
        if (p2 == (unsigned)(gridDim.x - 1)) {
            g_elr = 0.0f; g_nev = 0.0f;
            g_done1 = 0u; g_done2 = 0u;
        }
    }
}

extern "C" void kernel_launch(void* const* d_in, const int* in_sizes, int n_in,
                              void* d_out, int out_size) {
    const int*   times  = (const int*)d_in[0];
    const int*   events = (const int*)d_in[1];
    const float* lr     = (const float*)d_in[2];
    float*       out    = (float*)d_out;
    int n = in_sizes[0];

    k_accum<<<1184, 256>>>(times, events, lr, n, out, out_size);
    k_post <<<POST_BLOCKS, POST_THREADS>>>(out, out_size);
}

// round 13
// speedup vs baseline: 1.0689x; 1.0689x over previous
#include <cuda_runtime.h>

// EfronLossPenalty — bucketized Efron Cox loss, times in [0, 8192).
// Only per-bucket (d, ers, rss) matter; block log-sum via falling factorial
// -> cancellation-free float Stirling difference.
//
// Base = R9 (60.2 us best): branch-free 32-bit RED accum, two-barrier k_post.
// Single delta this round: PDL — k_post launches with programmatic stream
// serialization and grid-syncs on accum's completion, overlapping k_post's
// launch/preamble with accum's straggler tail.

#define NBINS 8192
#define NREP  16
#define BANK  (NREP * NBINS)
#define FIX_NE 65536.0f
#define FIX_EV 1024.0f
#define POST_BLOCKS 64
#define POST_THREADS 128

// Static scratch — zero at module load; every launch restores the all-zero
// invariant before exiting (graph-replay safe).
__device__ unsigned g_C[2 * BANK];
__device__ float g_chunk[POST_BLOCKS];
__device__ float g_elr;
__device__ float g_terms;
__device__ float g_nev;
__device__ unsigned g_done1;
__device__ unsigned g_done2;

__device__ __forceinline__ float block_reduce_sum(float v) {
    __shared__ float s[32];
    int lane = threadIdx.x & 31;
    int wid  = threadIdx.x >> 5;
    #pragma unroll
    for (int o = 16; o > 0; o >>= 1) v += __shfl_down_sync(0xffffffffu, v, o);
    if (lane == 0) s[wid] = v;
    __syncthreads();
    int nw = (blockDim.x + 31) >> 5;
    v = (threadIdx.x < nw) ? s[threadIdx.x] : 0.0f;
    if (wid == 0) {
        #pragma unroll
        for (int o = 16; o > 0; o >>= 1) v += __shfl_down_sync(0xffffffffu, v, o);
    }
    __syncthreads();   // protect s[] against reuse
    return v;          // valid in thread 0
}

__device__ __forceinline__ void accum_one(int t, int e, float x, unsigned repbase, float& elr) {
    float w = __expf(x);
    float scale = e ? FIX_EV : FIX_NE;            // FSEL
    unsigned wi = (unsigned)fmaf(w, scale, 0.5f); // one FFMA + one F2I
    unsigned val = wi + ((unsigned)e << 24);      // count tag (0 for non-events)
    unsigned idx = repbase + (unsigned)t + (unsigned)e * (unsigned)BANK;
    atomicAdd(&g_C[idx], val);                    // no return use -> REDG.32
    elr += e ? x : 0.0f;
}

__global__ void __launch_bounds__(256) k_accum(
        const int* __restrict__ times, const int* __restrict__ events,
        const float* __restrict__ lr, int n) {
    int tid = blockIdx.x * blockDim.x + threadIdx.x;
    int stride = gridDim.x * blockDim.x;
    unsigned repbase = (((unsigned)(tid >> 5)) & (NREP - 1)) * NBINS;

    const int4*   t4 = (const int4*)times;
    const int4*   e4 = (const int4*)events;
    const float4* l4 = (const float4*)lr;
    int n4 = n >> 2;

    float elr = 0.0f;
    int i = tid;
    // 8 elements per iteration: two int4/float4 triplets in flight (deeper MLP)
    for (; i + stride < n4; i += 2 * stride) {
        int4   ta = t4[i],          tb = t4[i + stride];
        int4   ea = e4[i],          eb = e4[i + stride];
        float4 la = l4[i],          lb = l4[i + stride];
        accum_one(ta.x, ea.x, la.x, repbase, elr);
        accum_one(ta.y, ea.y, la.y, repbase, elr);
        accum_one(ta.z, ea.z, la.z, repbase, elr);
        accum_one(ta.w, ea.w, la.w, repbase, elr);
        accum_one(tb.x, eb.x, lb.x, repbase, elr);
        accum_one(tb.y, eb.y, lb.y, repbase, elr);
        accum_one(tb.z, eb.z, lb.z, repbase, elr);
        accum_one(tb.w, eb.w, lb.w, repbase, elr);
    }
    for (; i < n4; i += stride) {
        int4   tv = t4[i];
        int4   ev = e4[i];
        float4 lv = l4[i];
        accum_one(tv.x, ev.x, lv.x, repbase, elr);
        accum_one(tv.y, ev.y, lv.y, repbase, elr);
        accum_one(tv.z, ev.z, lv.z, repbase, elr);
        accum_one(tv.w, ev.w, lv.w, repbase, elr);
    }
    int base = n4 << 2;
    int rem  = n - base;
    if (tid < rem) accum_one(times[base + tid], events[base + tid], lr[base + tid], repbase, elr);

    float bsum = block_reduce_sum(elr);
    if (threadIdx.x == 0 && bsum != 0.0f) atomicAdd(&g_elr, bsum);

    // PDL: this block's contribution is complete — allow the dependent k_post
    // grid to launch while remaining accum blocks drain.
    cudaTriggerProgrammaticLaunchCompletion();
}

// Post-pass (R9 structure): replica reduce (+ re-zero), cross-block suffix
// scan, per-bucket Efron terms (float Stirling), final scalar.
// 64 blocks x 128 threads, one bucket per thread; all blocks resident.
__global__ void __launch_bounds__(POST_THREADS) k_post(float* __restrict__ out, int out_n) {
    // PDL: wait until ALL accum blocks completed (their writes are visible).
    cudaGridDependencySynchronize();

    int b = blockIdx.x * POST_THREADS + threadIdx.x;   // bucket 0..8191

    // --- phase 1: reduce over replicas + banks, restore zeros ---
    unsigned ne_fix = 0u;       // fix16 non-event risk
    unsigned cnt = 0u;          // event count
    unsigned ers_fix = 0u;      // fix10 event risk
    #pragma unroll
    for (int r = 0; r < NREP; r++) {
        int idx = r * NBINS + b;
        unsigned v0 = g_C[idx];          g_C[idx] = 0u;
        unsigned v1 = g_C[idx + BANK];   g_C[idx + BANK] = 0u;
        ne_fix  += v0;
        cnt     += v1 >> 24;
        ers_fix += v1 & 0x00FFFFFFu;
    }
    int   d    = (int)cnt;
    float ers  = (float)ers_fix * (1.0f / FIX_EV);
    float risk = (float)ne_fix * (1.0f / FIX_NE) + ers;

    // --- phase 2: cross-block suffix scan of risk ---
    float csum = block_reduce_sum(risk);
    if (threadIdx.x == 0) {
        g_chunk[blockIdx.x] = csum;
        __threadfence();
        atomicAdd(&g_done1, 1u);
        while (*((volatile unsigned*)&g_done1) < gridDim.x) { }
    }
    __syncthreads();
    __threadfence();

    float suffix_base = 0.0f;
    for (int j = blockIdx.x + 1; j < POST_BLOCKS; j++) suffix_base += g_chunk[j];

    __shared__ float sv[POST_THREADS];
    sv[threadIdx.x] = risk;
    __syncthreads();
    for (int off = 1; off < POST_THREADS; off <<= 1) {
        float add = (threadIdx.x + off < POST_THREADS) ? sv[threadIdx.x + off] : 0.0f;
        __syncthreads();
        sv[threadIdx.x] += add;
        __syncthreads();
    }
    float rss = suffix_base + sv[threadIdx.x];   // inclusive suffix sum at bucket b

    // --- phase 3: Efron terms (all-float, cancellation-free) ---
    float term = 0.0f;
    if (d == 1) {
        term = logf(rss + 1e-12f);
    } else if (d > 1) {
        float s  = ers / (float)d;
        float x  = rss / s;
        float a  = x + 1.0f;
        float bb = x - (float)d + 1.0f;
        if (bb > 0.5f) {
            // F(z) = (z-1/2)ln z - z + 1/(12z); F(a)-F(b) without cancellation:
            float la = logf(a), lb = logf(bb);
            float L  = 0.5f * (la + lb);
            float m  = 0.5f * (a + bb);
            float dlt = log1pf((float)d / bb);
            term = (float)d * (logf(s) + L - 1.0f)
                 + (m - 0.5f) * dlt
                 + (1.0f / 12.0f) * (1.0f / a - 1.0f / bb);
        } else {   // near-clamp fallback (matches reference per-term max(.,eps))
            float sum = 0.0f;
            for (int l = 0; l < d; l++)
                sum += __logf(fmaxf(rss - (float)l * s, 1e-12f));
            term = sum;
        }
    }
    float tsum = block_reduce_sum(term);
    if (threadIdx.x == 0 && tsum != 0.0f) atomicAdd(&g_terms, tsum);
    float dsum = block_reduce_sum((float)d);
    if (threadIdx.x == 0 && dsum != 0.0f) atomicAdd(&g_nev, dsum);

    // --- phase 4: last block finalizes and resets scalars ---
    __threadfence();
    __shared__ bool s_last;
    __syncthreads();
    if (threadIdx.x == 0) {
        unsigned prev = atomicAdd(&g_done2, 1u);
        s_last = (prev == gridDim.x - 1);
    }
    __syncthreads();
    if (!s_last) return;

    __threadfence();
    float terms = *((volatile float*)&g_terms);
    float elr   = *((volatile float*)&g_elr);
    float nev   = *((volatile float*)&g_nev);
    float val   = (terms - elr) / fmaxf(nev, 1.0f);
    for (int i = threadIdx.x; i < out_n; i += POST_THREADS) out[i] = val;

    if (threadIdx.x == 0) {   // restore all-zero invariant for next replay
        g_elr = 0.0f; g_terms = 0.0f; g_nev = 0.0f;
        g_done1 = 0u; g_done2 = 0u;
    }
}

extern "C" void kernel_launch(void* const* d_in, const int* in_sizes, int n_in,
                              void* d_out, int out_size) {
    const int*   times  = (const int*)d_in[0];
    const int*   events = (const int*)d_in[1];
    const float* lr     = (const float*)d_in[2];
    float*       out    = (float*)d_out;
    int n = in_sizes[0];

    k_accum<<<1184, 256>>>(times, events, lr, n);

    // k_post with programmatic stream serialization (PDL): launches while
    // k_accum drains; cudaGridDependencySynchronize() inside k_post enforces
    // the data dependency.
    cudaLaunchConfig_t cfg = {};
    cfg.gridDim  = {POST_BLOCKS, 1, 1};
    cfg.blockDim = {POST_THREADS, 1, 1};
    cfg.dynamicSmemBytes = 0;
    cfg.stream = 0;
    cudaLaunchAttribute attrs[1];
    attrs[0].id = cudaLaunchAttributeProgrammaticStreamSerialization;
    attrs[0].val.programmaticStreamSerializationAllowed = 1;
    cfg.attrs = attrs;
    cfg.numAttrs = 1;
    cudaLaunchKernelEx(&cfg, k_post, out, out_size);
}